// round 2
// baseline (speedup 1.0000x reference)
#include <cuda_runtime.h>

// LatentODE2: B=8192, T=100, D=16, H=32, Hd=50, 2H=64, 10 Euler steps/t.
// Round-2 design: 1 warp = 1 CTA handles E=8 batch elements.
// - Lane j owns outputs {j, j+32} of each layer.
// - State (x, h, z) stored element-consecutive in SMEM: LDS.128 yields two
//   f32x2 register pairs directly (no packing on the state side).
// - All matmul FMAs are packed fp32 (fma.rn.f32x2 -> FFMA2): 2 MACs/issue.
// - Weights duplicated into (w,w) pairs in registers via mov.b64 (ALU pipe,
//   which was 5.6% idle in R1), 4 packs per k amortized over 16 FFMA2.

#define T_STEPS     100
#define D_IN        16
#define H_DIM       32
#define HD_DIM      50
#define EULER_STEPS 10
#define STEP_F      0.1f
#define DT_SCALER_F (1.0f / 24.0f)

#define E_PER_WARP  8
#define N_ELEMS     8192
#define GRID_BLOCKS (N_ELEMS / E_PER_WARP)   // 1024 CTAs x 32 threads

typedef unsigned long long u64;

__device__ __forceinline__ u64 pk2(float lo, float hi) {
    u64 r; asm("mov.b64 %0, {%1, %2};" : "=l"(r) : "f"(lo), "f"(hi)); return r;
}
__device__ __forceinline__ void up2(u64 v, float& a, float& b) {
    asm("mov.b64 {%0, %1}, %2;" : "=f"(a), "=f"(b) : "l"(v));
}
__device__ __forceinline__ void fma2(u64& d, u64 a, u64 b) {
    asm("fma.rn.f32x2 %0, %1, %2, %0;" : "+l"(d) : "l"(a), "l"(b));
}
__device__ __forceinline__ u64 add2(u64 a, u64 b) {
    u64 r; asm("add.rn.f32x2 %0, %1, %2;" : "=l"(r) : "l"(a), "l"(b)); return r;
}

__device__ __forceinline__ float my_tanh(float v) {
    v = fminf(fmaxf(v, -15.0f), 15.0f);
    float e = __expf(2.0f * v);
    return __fdividef(e - 1.0f, e + 1.0f);
}

// tanh both halves of a packed pair, return packed.
__device__ __forceinline__ u64 tanh2(u64 v) {
    float a, b; up2(v, a, b);
    return pk2(my_tanh(a), my_tanh(b));
}

__global__ void __launch_bounds__(32, 7)
latentode2_kernel(const float* __restrict__ dt,
                  const float* __restrict__ x,
                  const float* __restrict__ W1, const float* __restrict__ b1,
                  const float* __restrict__ W2, const float* __restrict__ b2,
                  const float* __restrict__ W3, const float* __restrict__ b3,
                  const float* __restrict__ W4, const float* __restrict__ b4,
                  float* __restrict__ out)
{
    // Weights (transposed, output-pair packed):
    //   sW1[k*32+j] = (W1[j][k], W1[j+32][k])   k<48, j<32 (0 past Hd)
    //   sW3[k*32+l] = (W3[l][k], W3[l+32][k])   k<32
    //   sW2[j*32+k] = W2[k][j]                  j<50
    __shared__ float2     sW1[48 * 32];
    __shared__ float2     sW3[32 * 32];
    __shared__ float      sW2[50 * 32];
    // State: [row][0] = elems 0..3 (two f32x2), [row][1] = elems 4..7.
    __shared__ ulonglong2 sH[H_DIM][2];
    __shared__ ulonglong2 sZ[HD_DIM][2];
    __shared__ ulonglong2 sX[D_IN][2];

    const int lane = threadIdx.x;   // 32 threads = 1 warp

    for (int idx = lane; idx < 48 * 32; idx += 32) {
        int k = idx >> 5, j = idx & 31;
        float a = W1[j * 48 + k];
        float b = (j + 32 < HD_DIM) ? W1[(j + 32) * 48 + k] : 0.0f;
        sW1[idx] = make_float2(a, b);
    }
    for (int idx = lane; idx < 32 * 32; idx += 32) {
        int k = idx >> 5, l = idx & 31;
        sW3[idx] = make_float2(W3[l * 32 + k], W3[(l + 32) * 32 + k]);
    }
    for (int idx = lane; idx < 50 * 32; idx += 32) {
        int j = idx >> 5, k = idx & 31;
        sW2[idx] = W2[k * 50 + j];
    }

    const int e0 = blockIdx.x * E_PER_WARP;

    // Per-lane constants (packed biases for accumulator init).
    const float b1a = b1[lane];
    const float b1b = (lane + 32 < HD_DIM) ? b1[lane + 32] : 0.0f;
    const u64 PB1a = pk2(b1a, b1a);
    const u64 PB1b = pk2(b1b, b1b);
    const float b3a = b3[lane], b3b = b3[lane + 32];
    const u64 PB3a = pk2(b3a, b3a);
    const u64 PB3b = pk2(b3b, b3b);
    const float b2o = b2[lane];
    const u64 PB2  = pk2(b2o, b2o);
    const float b4v = b4[0];
    const u64 PB4  = pk2(b4v, b4v);
    const float w4a = W4[lane];
    const float w4b = W4[lane + 32];

    // h state: packed pairs in registers + mirrored in SMEM (lane owns row=lane).
    u64 h01 = 0ull, h23 = 0ull, h45 = 0ull, h67 = 0ull;
    sH[lane][0] = make_ulonglong2(0ull, 0ull);
    sH[lane][1] = make_ulonglong2(0ull, 0ull);
    __syncwarp();

    const float2* dt2 = (const float2*)dt;

#pragma unroll 1
    for (int t = 0; t < T_STEPS; t++) {
        // x for this time step: lane k<16 gathers feature k for 8 elements.
        if (lane < D_IN) {
            float xv[E_PER_WARP];
#pragma unroll
            for (int e = 0; e < E_PER_WARP; e++)
                xv[e] = x[((e0 + e) * T_STEPS + t) * D_IN + lane];
            sX[lane][0] = make_ulonglong2(pk2(xv[0], xv[1]), pk2(xv[2], xv[3]));
            sX[lane][1] = make_ulonglong2(pk2(xv[4], xv[5]), pk2(xv[6], xv[7]));
        }
        // cs_e = STEP * (dt1-dt0) * DT_SCALER, redundantly in every lane (L1 bcast).
        float csv[E_PER_WARP];
#pragma unroll
        for (int e = 0; e < E_PER_WARP; e++) {
            float2 d = dt2[(e0 + e) * T_STEPS + t];
            csv[e] = STEP_F * ((d.y - d.x) * DT_SCALER_F);
        }
        const u64 cs01 = pk2(csv[0], csv[1]);
        const u64 cs23 = pk2(csv[2], csv[3]);
        const u64 cs45 = pk2(csv[4], csv[5]);
        const u64 cs67 = pk2(csv[6], csv[7]);
        __syncwarp();

        ulonglong2 yA = sX[0][0], yB = sX[0][1];
        u64 y01 = yA.x, y23 = yA.y, y45 = yB.x, y67 = yB.y;

#pragma unroll 1
        for (int s = 0; s < EULER_STEPS; s++) {
            u64 za01 = PB1a, za23 = PB1a, za45 = PB1a, za67 = PB1a;
            u64 zb01 = PB1b, zb23 = PB1b, zb45 = PB1b, zb67 = PB1b;
            u64 ga01 = PB3a, ga23 = PB3a, ga45 = PB3a, ga67 = PB3a;
            u64 gb01 = PB3b, gb23 = PB3b, gb45 = PB3b, gb67 = PB3b;

            // z1 += x @ W1[:, :16]^T
#pragma unroll
            for (int k = 0; k < D_IN; k++) {
                ulonglong2 vA = sX[k][0], vB = sX[k][1];
                float2 w = sW1[k * 32 + lane];
                u64 wxx = pk2(w.x, w.x), wyy = pk2(w.y, w.y);
                fma2(za01, vA.x, wxx); fma2(za23, vA.y, wxx);
                fma2(za45, vB.x, wxx); fma2(za67, vB.y, wxx);
                fma2(zb01, vA.x, wyy); fma2(zb23, vA.y, wyy);
                fma2(zb45, vB.x, wyy); fma2(zb67, vB.y, wyy);
            }
            // Fused: z1 += h @ W1[:, 16:48]^T ; g_pre = h @ W3^T
#pragma unroll
            for (int k = 0; k < H_DIM; k++) {
                ulonglong2 vA = sH[k][0], vB = sH[k][1];
                float2 w = sW1[(D_IN + k) * 32 + lane];
                float2 u = sW3[k * 32 + lane];
                u64 wxx = pk2(w.x, w.x), wyy = pk2(w.y, w.y);
                u64 uxx = pk2(u.x, u.x), uyy = pk2(u.y, u.y);
                fma2(za01, vA.x, wxx); fma2(za23, vA.y, wxx);
                fma2(za45, vB.x, wxx); fma2(za67, vB.y, wxx);
                fma2(zb01, vA.x, wyy); fma2(zb23, vA.y, wyy);
                fma2(zb45, vB.x, wyy); fma2(zb67, vB.y, wyy);
                fma2(ga01, vA.x, uxx); fma2(ga23, vA.y, uxx);
                fma2(ga45, vB.x, uxx); fma2(ga67, vB.y, uxx);
                fma2(gb01, vA.x, uyy); fma2(gb23, vA.y, uyy);
                fma2(gb45, vB.x, uyy); fma2(gb67, vB.y, uyy);
            }

            // z = tanh(za/zb), publish (lane owns rows lane and lane+32).
            sZ[lane][0] = make_ulonglong2(tanh2(za01), tanh2(za23));
            sZ[lane][1] = make_ulonglong2(tanh2(za45), tanh2(za67));
            if (lane + 32 < HD_DIM) {
                sZ[lane + 32][0] = make_ulonglong2(tanh2(zb01), tanh2(zb23));
                sZ[lane + 32][1] = make_ulonglong2(tanh2(zb45), tanh2(zb67));
            }

            // dy partial: tanh(g) @ W4^T, packed butterfly reduction.
            u64 p01, p23, p45, p67;
            {
                float a, b, c, d;
                up2(ga01, a, b); up2(gb01, c, d);
                p01 = pk2(fmaf(my_tanh(a), w4a, my_tanh(c) * w4b),
                          fmaf(my_tanh(b), w4a, my_tanh(d) * w4b));
                up2(ga23, a, b); up2(gb23, c, d);
                p23 = pk2(fmaf(my_tanh(a), w4a, my_tanh(c) * w4b),
                          fmaf(my_tanh(b), w4a, my_tanh(d) * w4b));
                up2(ga45, a, b); up2(gb45, c, d);
                p45 = pk2(fmaf(my_tanh(a), w4a, my_tanh(c) * w4b),
                          fmaf(my_tanh(b), w4a, my_tanh(d) * w4b));
                up2(ga67, a, b); up2(gb67, c, d);
                p67 = pk2(fmaf(my_tanh(a), w4a, my_tanh(c) * w4b),
                          fmaf(my_tanh(b), w4a, my_tanh(d) * w4b));
            }
#pragma unroll
            for (int off = 16; off > 0; off >>= 1) {
                p01 = add2(p01, __shfl_xor_sync(0xffffffffu, p01, off));
                p23 = add2(p23, __shfl_xor_sync(0xffffffffu, p23, off));
                p45 = add2(p45, __shfl_xor_sync(0xffffffffu, p45, off));
                p67 = add2(p67, __shfl_xor_sync(0xffffffffu, p67, off));
            }
            __syncwarp();   // z visible to all lanes

            // dh_pre = z @ W2^T (one output per lane).
            u64 d01 = PB2, d23 = PB2, d45 = PB2, d67 = PB2;
#pragma unroll
            for (int j = 0; j < HD_DIM; j++) {
                ulonglong2 zA = sZ[j][0], zB = sZ[j][1];
                float w = sW2[j * 32 + lane];
                u64 ww = pk2(w, w);
                fma2(d01, zA.x, ww); fma2(d23, zA.y, ww);
                fma2(d45, zB.x, ww); fma2(d67, zB.y, ww);
            }

            // y += cs * (p + b4) ; h += cs * tanh(dh_pre)
            fma2(y01, cs01, add2(p01, PB4));
            fma2(y23, cs23, add2(p23, PB4));
            fma2(y45, cs45, add2(p45, PB4));
            fma2(y67, cs67, add2(p67, PB4));
            fma2(h01, cs01, tanh2(d01));
            fma2(h23, cs23, tanh2(d23));
            fma2(h45, cs45, tanh2(d45));
            fma2(h67, cs67, tanh2(d67));

            __syncwarp();   // all lanes done reading old h
            sH[lane][0] = make_ulonglong2(h01, h23);
            sH[lane][1] = make_ulonglong2(h45, h67);
            __syncwarp();
        }

        // Output: lane e (<8) writes y_e. All lanes hold reduced y.
        if (lane < E_PER_WARP) {
            float y0, y1, y2, y3, y4, y5, y6, y7;
            up2(y01, y0, y1); up2(y23, y2, y3);
            up2(y45, y4, y5); up2(y67, y6, y7);
            float lo_half = (lane & 2) ? ((lane & 1) ? y3 : y2)
                                       : ((lane & 1) ? y1 : y0);
            float hi_half = (lane & 2) ? ((lane & 1) ? y7 : y6)
                                       : ((lane & 1) ? y5 : y4);
            float yv = (lane & 4) ? hi_half : lo_half;
            out[(e0 + lane) * T_STEPS + t] = yv;
        }
    }
}

extern "C" void kernel_launch(void* const* d_in, const int* in_sizes, int n_in,
                              void* d_out, int out_size) {
    (void)in_sizes; (void)n_in; (void)out_size;
    const float* dt = (const float*)d_in[0];
    const float* x  = (const float*)d_in[1];
    const float* W1 = (const float*)d_in[2];
    const float* b1 = (const float*)d_in[3];
    const float* W2 = (const float*)d_in[4];
    const float* b2 = (const float*)d_in[5];
    const float* W3 = (const float*)d_in[6];
    const float* b3 = (const float*)d_in[7];
    const float* W4 = (const float*)d_in[8];
    const float* b4 = (const float*)d_in[9];
    float* out = (float*)d_out;

    latentode2_kernel<<<GRID_BLOCKS, 32>>>(
        dt, x, W1, b1, W2, b2, W3, b3, W4, b4, out);
}